// round 13
// baseline (speedup 1.0000x reference)
#include <cuda_runtime.h>
#include <cuda_fp16.h>

// Problem constants
#define BN     8
#define DD     64
#define NN     3136        // H*W
#define KK     32
#define TPB    512         // 16 warps -> 4 per SMSP (reg cap 128)
#define REMOFF 3072        // 64-elem row tail, handled by warps 0-7
#define NBLK   128         // persistent, 1 block/SM, all resident
#define RPB    4           // rows per block: 128*4 = 512 = B*D
#define NW     (TPB / 32)  // 16 warps

typedef unsigned long long ull;

__device__ float    g_EM[BN * DD];
__device__ unsigned g_count = 0;    // monotonic epoch barrier (graph-replay safe)

__device__ __forceinline__ float ex2f(float x) {
    float r;
    asm("ex2.approx.ftz.f32 %0, %1;" : "=f"(r) : "f"(x));
    return r;
}
__device__ __forceinline__ __half2 h2ex2(__half2 x) {
    __half2 r;
    asm("ex2.approx.f16x2 %0, %1;" : "=r"(*(unsigned*)&r) : "r"(*(unsigned*)&x));
    return r;
}
__device__ __forceinline__ ull pack2(float lo, float hi) {
    ull r;
    asm("mov.b64 %0, {%1, %2};" : "=l"(r) : "f"(lo), "f"(hi));
    return r;
}
__device__ __forceinline__ void unpack2(ull v, float& lo, float& hi) {
    asm("mov.b64 {%0, %1}, %2;" : "=f"(lo), "=f"(hi) : "l"(v));
}
__device__ __forceinline__ ull fma2(ull a, ull b, ull c) {
    ull r;
    asm("fma.rn.f32x2 %0, %1, %2, %3;" : "=l"(r) : "l"(a), "l"(b), "l"(c));
    return r;
}
__device__ __forceinline__ ull add2(ull a, ull b) {
    ull r;
    asm("add.rn.f32x2 %0, %1, %2;" : "=l"(r) : "l"(a), "l"(b));
    return r;
}
__device__ __forceinline__ unsigned ld_acquire(const unsigned* p) {
    unsigned v;
    asm volatile("ld.global.acquire.gpu.u32 %0, [%1];" : "=r"(v) : "l"(p));
    return v;
}
__device__ __forceinline__ float ldcg_f(const float* p) {
    float v;
    asm volatile("ld.global.cg.f32 %0, [%1];" : "=f"(v) : "l"(p));
    return v;
}

// exp2 poly (deg-4, |f|<=0.5, rel err ~1e-6) — R10-proven
#define EC1 0.69314718f
#define EC2 0.24022650f
#define EC3 0.05550411f
#define EC4 0.00961804f
#define EMAGIC 12582912.0f   // 1.5 * 2^23

// 4 half2 broadcast constants in one 16B smem word: {a2, b2, c2, cw2}
struct __align__(16) HC { __half2 a, b, c, w; };

__global__ __launch_bounds__(TPB, 1)
void enc_fused(const float* __restrict__ X,
               const float* __restrict__ codewords,
               const float* __restrict__ scale,
               const float* __restrict__ fc_w,
               const float* __restrict__ fc_b,
               float* __restrict__ out)
{
    __shared__ HC         cH[RPB][KK];    // half2 consts (MUFU path)
    __shared__ ulonglong2 cAB[RPB][KK];   // {(a,a),(b,b)} f32x2 (poly path)
    __shared__ ulonglong2 cCW[RPB][KK];   // {(c,c),(cw,cw)} f32x2 (poly path)
    __shared__ float4     cS[RPB][KK];    // scalar f32 consts (tail pass)
    __shared__ float      wsum[2][NW];
    __shared__ float      tsum[8];
    __shared__ float      sEM[DD];
    __shared__ float      sG[RPB];

    const int tid  = threadIdx.x;
    const int wid  = tid >> 5;
    const int lane = tid & 31;
    const int bd0  = blockIdx.x * RPB;    // 4 consecutive bd, same b
    const int b    = bd0 >> 6;

    // packed poly constants (loop-invariant registers)
    const ull P_C1   = pack2(EC1, EC1);
    const ull P_C2   = pack2(EC2, EC2);
    const ull P_C3   = pack2(EC3, EC3);
    const ull P_C4   = pack2(EC4, EC4);
    const ull P_ONE  = pack2(1.0f, 1.0f);
    const ull P_NEG1 = pack2(-1.0f, -1.0f);
    const ull P_MAG  = pack2(EMAGIC, EMAGIC);
    const ull P_NMAG = pack2(-EMAGIC, -EMAGIC);

    // ---- preload all 4 rows' constants once ----
    if (tid < RPB * KK) {
        const int r = tid >> 5, k = tid & 31;
        const int d = (bd0 + r) & (DD - 1);
        const float L2E = 1.4426950408889634f;
        float s  = scale[k * DD + d] * L2E;
        float c  = codewords[k * DD + d];
        float bb = -2.0f * s * c;
        float cc = s * c * c;
        HC h;
        h.a = __float2half2_rn(s);
        h.b = __float2half2_rn(bb);
        h.c = __float2half2_rn(cc);
        h.w = __float2half2_rn(c);
        cH[r][k]  = h;
        cAB[r][k] = make_ulonglong2(pack2(s, s),   pack2(bb, bb));
        cCW[r][k] = make_ulonglong2(pack2(cc, cc), pack2(c, c));
        cS[r][k]  = make_float4(s, bb, cc, c);
    }

    // ---- row-0 X loads: 3 float2 pairs (6 elems) ----
    float2 xc[3];
    {
        const float2* xr = (const float2*)(X + (size_t)bd0 * NN);
        #pragma unroll
        for (int p = 0; p < 3; p++) xc[p] = xr[tid + p * TPB];
    }
    // tail element: warps 0-7 own row (wid>>1), half (wid&1)
    float xrem = 0.0f;
    const int trow = wid >> 1;
    const int tcol = REMOFF + (wid & 1) * 32 + lane;
    if (wid < 8) xrem = X[(size_t)(bd0 + trow) * NN + tcol];

    __syncthreads();

    // ---- tail pass: 8 warps (2 per SMSP), scalar f32 MUFU loop ----
    float Erem = 0.0f;
    if (wid < 8) {
        float se = 0.0f, sc_ = 0.0f;
        #pragma unroll 4
        for (int k = 0; k < KK; k++) {
            float4 q = cS[trow][k];
            float t = fmaf(fmaf(q.x, xrem, q.y), xrem, q.z);
            float e = ex2f(t);
            se += e;
            sc_ = fmaf(e, q.w, sc_);
        }
        Erem = xrem - __fdividef(sc_, se);
        float rs = Erem;
        #pragma unroll
        for (int off = 16; off; off >>= 1)
            rs += __shfl_xor_sync(0xffffffffu, rs, off);
        if (lane == 0) tsum[wid] = rs;
    }

    // ---- main rows: pairs 0,1 -> f16x2 MUFU; pair 2 -> f32x2 poly on FMA ----
    float Ereg[RPB][6];

    #pragma unroll
    for (int r = 0; r < RPB; r++) {
        const int bd = bd0 + r;

        // prefetch next row behind this row's k-loop
        float2 xn[3];
        const bool more = (r + 1 < RPB);
        if (more) {
            const float2* xr = (const float2*)(X + (size_t)(bd + 1) * NN);
            #pragma unroll
            for (int p = 0; p < 3; p++) xn[p] = xr[tid + p * TPB];
        }

        __half2 xh[2], seh[2], sch[2];
        #pragma unroll
        for (int p = 0; p < 2; p++) {
            xh[p]  = __floats2half2_rn(xc[p].x, xc[p].y);
            seh[p] = __float2half2_rn(0.0f);
            sch[p] = __float2half2_rn(0.0f);
        }
        const ull x2p = pack2(xc[2].x, xc[2].y);
        ull seP = 0ull, scP = 0ull;

        #pragma unroll 4
        for (int k = 0; k < KK; k++) {
            HC h = cH[r][k];
            ulonglong2 qab = cAB[r][k];
            ulonglong2 qcw = cCW[r][k];

            // MUFU path: 2 half2 (4 elems)
            #pragma unroll
            for (int p = 0; p < 2; p++) {
                __half2 t = __hfma2(__hfma2(h.a, xh[p], h.b), xh[p], h.c);
                __half2 e = h2ex2(t);
                seh[p] = __hadd2(seh[p], e);
                sch[p] = __hfma2(e, h.w, sch[p]);
            }

            // FMA-pipe poly path: 1 f32x2 (2 elems)
            {
                ull t2 = fma2(fma2(qab.x, x2p, qab.y), x2p, qcw.x);
                ull m2 = add2(t2, P_MAG);            // RN -> round(t) in mantissa
                ull i2 = add2(m2, P_NMAG);           // i_f = round(t)
                ull f2 = fma2(i2, P_NEG1, t2);       // f = t - i, |f| <= 0.5
                ull p2 = fma2(P_C4, f2, P_C3);
                p2     = fma2(p2, f2, P_C2);
                p2     = fma2(p2, f2, P_C1);
                p2     = fma2(p2, f2, P_ONE);        // 2^f
                float ml, mh, pl, ph;
                unpack2(m2, ml, mh);
                unpack2(p2, pl, ph);
                int rl = __float_as_int(pl) + (__float_as_int(ml) << 23);
                int rh = __float_as_int(ph) + (__float_as_int(mh) << 23);
                ull e2 = pack2(__int_as_float(rl), __int_as_float(rh));
                seP = add2(seP, e2);
                scP = fma2(e2, qcw.y, scP);
            }
        }

        // epilogue: E = x - sc/se (f32), keep in regs; row-sum -> g_EM
        float esum = 0.0f;
        #pragma unroll
        for (int p = 0; p < 2; p++) {
            float2 seF = __half22float2(seh[p]);
            float2 scF = __half22float2(sch[p]);
            float El = xc[p].x - __fdividef(scF.x, seF.x);
            float Eh = xc[p].y - __fdividef(scF.y, seF.y);
            Ereg[r][2 * p]     = El;
            Ereg[r][2 * p + 1] = Eh;
            esum += El + Eh;
        }
        {
            float sel, seh2, scl, sch2;
            unpack2(seP, sel, seh2);
            unpack2(scP, scl, sch2);
            float El = xc[2].x - __fdividef(scl, sel);
            float Eh = xc[2].y - __fdividef(sch2, seh2);
            Ereg[r][4] = El;
            Ereg[r][5] = Eh;
            esum += El + Eh;
        }

        #pragma unroll
        for (int off = 16; off; off >>= 1)
            esum += __shfl_xor_sync(0xffffffffu, esum, off);
        if (lane == 0) wsum[r & 1][wid] = esum;
        __syncthreads();
        if (tid < 32) {
            float s = (lane < NW) ? wsum[r & 1][lane] : 0.0f;
            #pragma unroll
            for (int off = 16; off; off >>= 1)
                s += __shfl_xor_sync(0xffffffffu, s, off);
            if (lane == 0)
                g_EM[bd] = (s + tsum[2 * r] + tsum[2 * r + 1]) * (1.0f / KK);
        }

        if (more) {
            #pragma unroll
            for (int p = 0; p < 3; p++) xc[p] = xn[p];
        }
    }

    // ---- grid barrier (128 blocks, all resident; monotonic epoch) ----
    __threadfence();
    __syncthreads();
    if (tid == 0) {
        unsigned old = atomicAdd(&g_count, 1u);
        unsigned target = (old / NBLK + 1u) * NBLK;
        while (ld_acquire(&g_count) < target)
            __nanosleep(64);
    }
    __syncthreads();

    // ---- gamma for this block's 4 rows (same b) ----
    if (tid < DD) sEM[tid] = ldcg_f(&g_EM[b * DD + tid]);
    __syncthreads();
    if (tid < RPB) {
        const int d = (bd0 + tid) & (DD - 1);
        float acc = fc_b[d];
        const float* wrow = fc_w + d * DD;
        #pragma unroll
        for (int i = 0; i < DD; i++)
            acc = fmaf(sEM[i], wrow[i], acc);
        sG[tid] = 1.0f + 1.0f / (1.0f + __expf(-acc));   // 1 + sigmoid
    }
    __syncthreads();

    // ---- final: out = relu(E * (1 + gamma)), STG.64 pairs ----
    #pragma unroll
    for (int r = 0; r < RPB; r++) {
        const float g = sG[r];
        float2* ob = (float2*)(out + (size_t)(bd0 + r) * NN);
        #pragma unroll
        for (int p = 0; p < 3; p++) {
            float vx = Ereg[r][2 * p]     * g;
            float vy = Ereg[r][2 * p + 1] * g;
            float2 v;
            v.x = vx > 0.0f ? vx : 0.0f;
            v.y = vy > 0.0f ? vy : 0.0f;
            ob[tid + p * TPB] = v;
        }
    }
    if (wid < 8) {
        float v = Erem * sG[trow];
        out[(size_t)(bd0 + trow) * NN + tcol] = v > 0.0f ? v : 0.0f;
    }
}

extern "C" void kernel_launch(void* const* d_in, const int* in_sizes, int n_in,
                              void* d_out, int out_size)
{
    const float* X  = (const float*)d_in[0];
    const float* cw = (const float*)d_in[1];
    const float* sc = (const float*)d_in[2];
    const float* fw = (const float*)d_in[3];
    const float* fb = (const float*)d_in[4];
    float* out = (float*)d_out;

    enc_fused<<<NBLK, TPB>>>(X, cw, sc, fw, fb, out);
}